// round 17
// baseline (speedup 1.0000x reference)
#include <cuda_runtime.h>
#include <cuda_bf16.h>
#include <math.h>
#include <stdint.h>

#define B_  128
#define T_  1024
#define NX_ 256
#define NH_ 512
#define NY_ 256

// Progress flags: g_flag2[bt][group][jt], row padded to 32 words (128B).
__device__ unsigned g_flag2[16][2][32];

// ---------------------------------------------------------------------------
// Helpers
// ---------------------------------------------------------------------------
__device__ __forceinline__ void ffma2(unsigned long long& d,
                                      unsigned long long a, unsigned long long b)
{
    asm("fma.rn.f32x2 %0, %1, %2, %0;" : "+l"(d) : "l"(a), "l"(b));
}
__device__ __forceinline__ void unpack2(unsigned long long v, float& lo, float& hi)
{
    asm("mov.b64 {%0, %1}, %2;" : "=f"(lo), "=f"(hi) : "l"(v));
}
__device__ __forceinline__ unsigned ld_acq(const unsigned* p)
{
    unsigned v;
    asm volatile("ld.global.acquire.gpu.u32 %0, [%1];" : "=r"(v) : "l"(p) : "memory");
    return v;
}
__device__ __forceinline__ unsigned ld_rlx(const unsigned* p)
{
    unsigned v;
    asm volatile("ld.global.relaxed.gpu.u32 %0, [%1];" : "=r"(v) : "l"(p) : "memory");
    return v;
}
__device__ __forceinline__ void st_rel(unsigned* p, unsigned v)
{
    asm volatile("st.global.release.gpu.u32 [%0], %1;" :: "l"(p), "r"(v) : "memory");
}

__device__ __forceinline__ unsigned bf16_pair(float f0, float f1)
{
    unsigned u0 = __bfloat16_as_ushort(__float2bfloat16_rn(f0));
    unsigned u1 = __bfloat16_as_ushort(__float2bfloat16_rn(f1));
    return u0 | (u1 << 16);
}
__device__ __forceinline__ unsigned bf16_hi_pair(float f0, float f1,
                                                 float& r0, float& r1)
{
    __nv_bfloat16 h0 = __float2bfloat16_rn(f0);
    __nv_bfloat16 h1 = __float2bfloat16_rn(f1);
    r0 = f0 - __bfloat162float(h0);
    r1 = f1 - __bfloat162float(h1);
    return (unsigned)__bfloat16_as_ushort(h0) |
           ((unsigned)__bfloat16_as_ushort(h1) << 16);
}

__device__ __forceinline__ void mma_bf16(float& c0, float& c1, float& c2, float& c3,
    unsigned a0, unsigned a1, unsigned a2, unsigned a3, unsigned b0, unsigned b1)
{
    asm volatile(
        "mma.sync.aligned.m16n8k16.row.col.f32.bf16.bf16.f32 "
        "{%0,%1,%2,%3}, {%4,%5,%6,%7}, {%8,%9}, {%0,%1,%2,%3};"
        : "+f"(c0), "+f"(c1), "+f"(c2), "+f"(c3)
        : "r"(a0), "r"(a1), "r"(a2), "r"(a3), "r"(b0), "r"(b1));
}

__device__ __forceinline__ void ldsm_x4(unsigned& r0, unsigned& r1,
                                        unsigned& r2, unsigned& r3, unsigned addr)
{
    asm volatile("ldmatrix.sync.aligned.m8n8.x4.shared.b16 {%0,%1,%2,%3}, [%4];"
                 : "=r"(r0), "=r"(r1), "=r"(r2), "=r"(r3) : "r"(addr));
}

// ---------------------------------------------------------------------------
// bf16-split tensor-core NT GEMM v2: ldmatrix fragments + LDG double buffer.
// C[m][n] = sum_k A[m][k] * B[n][k]; 3-product split (hh + hl + lh).
// CTA tile 128(m) x 64(n), BK=16, 256 threads = 8 warps (4m x 2n).
// SMEM u32 stride 12: ldmatrix row addrs 12r mod 32 distinct -> conflict-free.
// ---------------------------------------------------------------------------
__global__ __launch_bounds__(256) void sgemm_bf16s2(
    const float* __restrict__ A,
    const float* __restrict__ Bm,
    float* __restrict__ C,
    int M, int N, int K)
{
    __shared__ __align__(16) unsigned Ah[128 * 12];
    __shared__ __align__(16) unsigned Al[128 * 12];
    __shared__ __align__(16) unsigned Bh[64 * 12];
    __shared__ __align__(16) unsigned Bl[64 * 12];

    const int tid  = threadIdx.x;
    const int lane = tid & 31;
    const int wid  = tid >> 5;
    const int g    = lane >> 2;
    const int t4   = lane & 3;
    const int wm   = (wid & 3) * 32;
    const int wn   = (wid >> 2) * 32;
    const long m0  = (long)blockIdx.y * 128;
    const int  n0  = blockIdx.x * 64;

    const int r8 = tid >> 3;
    const int c8 = tid & 7;

    // ---- loop-invariant ldmatrix addresses ----
    const int sub = lane >> 3;        // 0..3
    const int rr8 = lane & 7;         // 0..7
    unsigned aaddr_h[2], aaddr_l[2], baddr_h[2], baddr_l[2];
#pragma unroll
    for (int mt = 0; mt < 2; ++mt) {
        int idx = (wm + mt * 16 + (sub & 1) * 8 + rr8) * 12 + (sub >> 1) * 4;
        aaddr_h[mt] = (unsigned)__cvta_generic_to_shared(&Ah[idx]);
        aaddr_l[mt] = (unsigned)__cvta_generic_to_shared(&Al[idx]);
    }
#pragma unroll
    for (int s = 0; s < 2; ++s) {
        int idx = (wn + (2 * s + (sub >> 1)) * 8 + rr8) * 12 + (sub & 1) * 4;
        baddr_h[s] = (unsigned)__cvta_generic_to_shared(&Bh[idx]);
        baddr_l[s] = (unsigned)__cvta_generic_to_shared(&Bl[idx]);
    }

    float acc[2][4][4];
#pragma unroll
    for (int mt = 0; mt < 2; ++mt)
#pragma unroll
        for (int nt = 0; nt < 4; ++nt)
#pragma unroll
            for (int i = 0; i < 4; ++i) acc[mt][nt][i] = 0.0f;

    // ---- prologue: load chunk 0 into registers ----
    float2 av[4], bv[2];
#pragma unroll
    for (int q = 0; q < 4; ++q)
        av[q] = *(const float2*)(A + (m0 + r8 + q * 32) * K + c8 * 2);
#pragma unroll
    for (int q = 0; q < 2; ++q)
        bv[q] = *(const float2*)(Bm + (long)(n0 + r8 + q * 32) * K + c8 * 2);

    for (int kc = 0; kc < K; kc += 16) {
        // ---- STS with bf16 split conversion ----
#pragma unroll
        for (int q = 0; q < 4; ++q) {
            int rr = r8 + q * 32;
            float r0, r1;
            unsigned h = bf16_hi_pair(av[q].x, av[q].y, r0, r1);
            Ah[rr * 12 + c8] = h;
            Al[rr * 12 + c8] = bf16_pair(r0, r1);
        }
#pragma unroll
        for (int q = 0; q < 2; ++q) {
            int rr = r8 + q * 32;
            float r0, r1;
            unsigned h = bf16_hi_pair(bv[q].x, bv[q].y, r0, r1);
            Bh[rr * 12 + c8] = h;
            Bl[rr * 12 + c8] = bf16_pair(r0, r1);
        }
        __syncthreads();

        // ---- prefetch next chunk (drains under LDSM + HMMA) ----
        if (kc + 16 < K) {
#pragma unroll
            for (int q = 0; q < 4; ++q)
                av[q] = *(const float2*)(A + (m0 + r8 + q * 32) * K + kc + 16 + c8 * 2);
#pragma unroll
            for (int q = 0; q < 2; ++q)
                bv[q] = *(const float2*)(Bm + (long)(n0 + r8 + q * 32) * K + kc + 16 + c8 * 2);
        }

        // ---- ldmatrix fragment loads (8 x LDSM.x4) ----
        unsigned ah[2][4], al[2][4], bhf[2][4], blf[2][4];
#pragma unroll
        for (int mt = 0; mt < 2; ++mt) {
            ldsm_x4(ah[mt][0], ah[mt][1], ah[mt][2], ah[mt][3], aaddr_h[mt]);
            ldsm_x4(al[mt][0], al[mt][1], al[mt][2], al[mt][3], aaddr_l[mt]);
        }
#pragma unroll
        for (int s = 0; s < 2; ++s) {
            ldsm_x4(bhf[s][0], bhf[s][1], bhf[s][2], bhf[s][3], baddr_h[s]);
            ldsm_x4(blf[s][0], blf[s][1], blf[s][2], blf[s][3], baddr_l[s]);
        }
        // b fragment for nt: regs bhf[nt>>1][(nt&1)*2], bhf[nt>>1][(nt&1)*2+1]

        // ---- 3 products (hh, hl, lh), product-outer ----
#pragma unroll
        for (int mt = 0; mt < 2; ++mt)
#pragma unroll
            for (int nt = 0; nt < 4; ++nt)
                mma_bf16(acc[mt][nt][0], acc[mt][nt][1], acc[mt][nt][2], acc[mt][nt][3],
                         ah[mt][0], ah[mt][1], ah[mt][2], ah[mt][3],
                         bhf[nt >> 1][(nt & 1) * 2], bhf[nt >> 1][(nt & 1) * 2 + 1]);
#pragma unroll
        for (int mt = 0; mt < 2; ++mt)
#pragma unroll
            for (int nt = 0; nt < 4; ++nt)
                mma_bf16(acc[mt][nt][0], acc[mt][nt][1], acc[mt][nt][2], acc[mt][nt][3],
                         ah[mt][0], ah[mt][1], ah[mt][2], ah[mt][3],
                         blf[nt >> 1][(nt & 1) * 2], blf[nt >> 1][(nt & 1) * 2 + 1]);
#pragma unroll
        for (int mt = 0; mt < 2; ++mt)
#pragma unroll
            for (int nt = 0; nt < 4; ++nt)
                mma_bf16(acc[mt][nt][0], acc[mt][nt][1], acc[mt][nt][2], acc[mt][nt][3],
                         al[mt][0], al[mt][1], al[mt][2], al[mt][3],
                         bhf[nt >> 1][(nt & 1) * 2], bhf[nt >> 1][(nt & 1) * 2 + 1]);

        __syncthreads();
    }

    // ---- epilogue ----
#pragma unroll
    for (int mt = 0; mt < 2; ++mt) {
#pragma unroll
        for (int nt = 0; nt < 4; ++nt) {
            long row = m0 + wm + mt * 16 + g;
            int  col = n0 + wn + nt * 8 + t4 * 2;
            *(float2*)(C + row * N + col) =
                make_float2(acc[mt][nt][0], acc[mt][nt][1]);
            *(float2*)(C + (row + 8) * N + col) =
                make_float2(acc[mt][nt][2], acc[mt][nt][3]);
        }
    }
}

// ---------------------------------------------------------------------------
// Sequential recurrence v10 (FROZEN — R15 best): temporal 2-group phase
// shift, register-resident Wh, relaxed post-kloop flag read with branch-gated
// speculative h prefetch, acquire-poll slow path.
// ---------------------------------------------------------------------------
#define NTHR     256
#define HTW_STR  272
#define RED_FOFF (16 * HTW_STR)
#define SMEM_BYTES (RED_FOFF * 4 + 2 * 2048 * 8)   // 50176

__global__ __launch_bounds__(NTHR, 1) void rnn_seq10(
    const float* __restrict__ Wh,
    const float* __restrict__ h0,
    float* __restrict__ hs)
{
    extern __shared__ float sm[];

    const int tid  = threadIdx.x;
    const int wid  = tid >> 5;
    const int lane = tid & 31;

    const int jt  = blockIdx.x & 7;
    const int bt  = blockIdx.x >> 3;
    const int j0g = jt * 64;
    const int b0  = bt * 8;
    const int kw0 = wid * 64;

    unsigned long long W[64];
#pragma unroll
    for (int c = 0; c < 2; ++c) {
        const float* row = Wh + (size_t)(j0g + lane * 2 + c) * NH_ + kw0;
#pragma unroll
        for (int q = 0; q < 16; ++q) {
            ulonglong2 v = *(const ulonglong2*)(row + q * 4);
            W[c * 32 + 2 * q]     = v.x;
            W[c * 32 + 2 * q + 1] = v.y;
        }
    }

    const int rb = lane >> 3;
    const int f4 = (lane & 7) * 8;
    const int eb = tid >> 6;
    const int ej = tid & 63;

    float4 hx0, hx1;
    {
        const float* src = h0 + (size_t)(b0 + rb) * NH_ + kw0 + f4;
        hx0 = __ldcg((const float4*)src);
        hx1 = __ldcg((const float4*)(src + 4));
    }

    for (int p = 0; p < 2 * T_; ++p) {
        const int g = p & 1;
        const int t = p >> 1;
        unsigned* flags = &g_flag2[bt][g][0];
        float* hTw = sm + (wid * 2 + g) * HTW_STR;
        unsigned long long* red =
            (unsigned long long*)(sm + RED_FOFF) + (size_t)g * 2048;
        const int b0g = b0 + g * 4;

        float pre = __ldcg(hs + ((size_t)(b0g + eb) * T_ + t) * NH_ + j0g + ej);

        *(float4*)&hTw[rb * 68 + f4]     = hx0;
        *(float4*)&hTw[rb * 68 + f4 + 4] = hx1;
        __syncwarp();

        unsigned long long acc[4][2];
#pragma unroll
        for (int b = 0; b < 4; ++b) { acc[b][0] = 0ull; acc[b][1] = 0ull; }

#pragma unroll
        for (int b = 0; b < 4; ++b) {
            const float* hb = &hTw[b * 68];
#pragma unroll
            for (int q = 0; q < 16; ++q) {
                ulonglong2 va = *(const ulonglong2*)(hb + q * 4);
                ffma2(acc[b][0], va.x, W[2 * q]);
                ffma2(acc[b][0], va.y, W[2 * q + 1]);
                ffma2(acc[b][1], va.x, W[32 + 2 * q]);
                ffma2(acc[b][1], va.y, W[32 + 2 * q + 1]);
            }
        }

        const unsigned* f2p = nullptr;
        const float* nsrc = nullptr;
        bool pending = false;
        int t2 = 0;
        if (p + 1 < 2 * T_) {
            const int g2 = g ^ 1;
            t2 = (p + 1) >> 1;
            const int b0g2 = b0 + g2 * 4;
            if (t2 == 0) {
                nsrc = h0 + (size_t)(b0g2 + rb) * NH_ + kw0 + f4;
                hx0 = __ldcg((const float4*)nsrc);
                hx1 = __ldcg((const float4*)(nsrc + 4));
            } else {
                f2p = &g_flag2[bt][g2][0] + wid;
                unsigned vflag = ld_rlx(f2p);
                nsrc = hs + ((size_t)(b0g2 + rb) * T_ + (t2 - 1)) * NH_ + kw0 + f4;
                if ((vflag - (unsigned)t2) <= 1u) {
                    hx0 = __ldcg((const float4*)nsrc);
                    hx1 = __ldcg((const float4*)(nsrc + 4));
                } else {
                    pending = true;
                }
            }
        }

#pragma unroll
        for (int b = 0; b < 4; ++b) {
            ulonglong2 v; v.x = acc[b][0]; v.y = acc[b][1];
            *(ulonglong2*)&red[(size_t)wid * 256 + b * 64 + lane * 2] = v;
        }
        __syncthreads();

        {
            float s = pre;
#pragma unroll
            for (int w = 0; w < 8; ++w) {
                float lo, hi;
                unpack2(red[(size_t)w * 256 + eb * 64 + ej], lo, hi);
                s += lo + hi;
            }
            float hv = tanhf(s);
            hs[((size_t)(b0g + eb) * T_ + t) * NH_ + j0g + ej] = hv;
        }

        __syncthreads();
        if (tid == 0) st_rel(flags + jt, (unsigned)(t + 1));

        if (pending) {
            for (;;) {
                unsigned v = ld_acq(f2p);
                if ((v - (unsigned)t2) <= 1u) break;
                __nanosleep(20);
            }
            hx0 = __ldcg((const float4*)nsrc);
            hx1 = __ldcg((const float4*)(nsrc + 4));
        }
    }
}

// ---------------------------------------------------------------------------
// Launch: [sgemm_bf16s2(pre), rnn_seq10, sgemm_bf16s2(y)]
// ---------------------------------------------------------------------------
extern "C" void kernel_launch(void* const* d_in, const int* in_sizes, int n_in,
                              void* d_out, int out_size)
{
    const float* x  = (const float*)d_in[0];
    const float* h0 = (const float*)d_in[1];
    const float* Wi = (const float*)d_in[2];
    const float* Wh = (const float*)d_in[3];
    const float* Wy = (const float*)d_in[4];

    float* y  = (float*)d_out;
    float* hs = y + (size_t)B_ * T_ * NY_;

    // Phase 1: pre = x @ Wi^T -> hs region (scratch)
    {
        dim3 grid(NH_ / 64, (B_ * T_) / 128);
        sgemm_bf16s2<<<grid, 256>>>(x, Wi, hs, B_ * T_, NH_, NX_);
    }
    // Phase 2: sequential recurrence (frozen R15 best)
    {
        cudaFuncSetAttribute(rnn_seq10,
                             cudaFuncAttributeMaxDynamicSharedMemorySize, SMEM_BYTES);
        rnn_seq10<<<128, NTHR, SMEM_BYTES>>>(Wh, h0, hs);
    }
    // Phase 3: y = hs @ Wy^T
    {
        dim3 grid(NY_ / 64, (B_ * T_) / 128);
        sgemm_bf16s2<<<grid, 256>>>(hs, Wy, y, B_ * T_, NY_, NH_);
    }
}